// round 5
// baseline (speedup 1.0000x reference)
#include <cuda_runtime.h>

#define NMAX 16384
#define KNN  16
#define CDIM 64
#define NODES_PER_BLOCK 4

#define KNN_WARPS 16          // queries per block (one warp each)
#define KNN_THREADS (KNN_WARPS * 32)
#define KNN_TILE 2048         // candidates per smem tile (32KB packed)

#define FULLMASK 0xffffffffu
#define FINF __int_as_float(0x7f800000)

// ---- scratch (no allocation allowed) ----
__device__ float4 g_pos4[NMAX];
__device__ int    g_knn[NMAX * KNN];
__device__ float  g_B[NMAX * CDIM];   // x @ W1b
__device__ float  g_C[NMAX * CDIM];   // x @ (W1a - W1b) + b1

// ---- packed f32x2 helpers ----
__device__ __forceinline__ unsigned long long pk2(float a, float b) {
    unsigned long long r;
    asm("mov.b64 %0, {%1, %2};" : "=l"(r) : "f"(a), "f"(b));
    return r;
}
__device__ __forceinline__ void upk2(unsigned long long v, float& a, float& b) {
    asm("mov.b64 {%0, %1}, %2;" : "=f"(a), "=f"(b) : "l"(v));
}
__device__ __forceinline__ unsigned long long fma2(unsigned long long a,
                                                   unsigned long long b,
                                                   unsigned long long c) {
    unsigned long long r;
    asm("fma.rn.f32x2 %0, %1, %2, %3;" : "=l"(r) : "l"(a), "l"(b), "l"(c));
    return r;
}
__device__ __forceinline__ unsigned long long mul2(unsigned long long a,
                                                   unsigned long long b) {
    unsigned long long r;
    asm("mul.rn.f32x2 %0, %1, %2;" : "=l"(r) : "l"(a), "l"(b));
    return r;
}
__device__ __forceinline__ unsigned long long add2(unsigned long long a,
                                                   unsigned long long b) {
    unsigned long long r;
    asm("add.rn.f32x2 %0, %1, %2;" : "=l"(r) : "l"(a), "l"(b));
    return r;
}

// ============================================================
// Kernel 0: pack pos -> (x,y,z, |p|^2)
// ============================================================
__global__ void pack_pos_kernel(const float* __restrict__ pos, int n) {
    int i = blockIdx.x * blockDim.x + threadIdx.x;
    if (i < n) {
        float x = pos[i * 3 + 0];
        float y = pos[i * 3 + 1];
        float z = pos[i * 3 + 2];
        g_pos4[i] = make_float4(x, y, z, fmaf(x, x, fmaf(y, y, z * z)));
    }
}

// ============================================================
// Kernel 1: brute-force KNN — warp per query, packed f32x2 distances.
// Lane evaluates 2 candidates per step (5 packed ops), one ballot per
// 64 candidates. Warp-distributed sorted top-16 with warp-uniform
// shfl-up inserts. Self-exclusion deferred to the rare insert path.
// ============================================================
__device__ __forceinline__ void warp_insert(float dn, int jn,
                                            float& bd, int& bj,
                                            float& worst, int lane) {
    float bp = __shfl_up_sync(FULLMASK, bd, 1);
    int   ip = __shfl_up_sync(FULLMASK, bj, 1);
    unsigned gm = __ballot_sync(FULLMASK, (lane < KNN) && (bd > dn));
    int pos = __ffs(gm) - 1;            // gm != 0 since bd[15] > dn
    if (lane < KNN) {
        if (lane > pos)       { bd = bp; bj = ip; }
        else if (lane == pos) { bd = dn; bj = jn; }
    }
    worst = __shfl_sync(FULLMASK, bd, KNN - 1);
}

__global__ __launch_bounds__(KNN_THREADS, 4)
void knn_kernel(int n) {
    __shared__ ulonglong2 tileA[KNN_TILE / 2];  // (x-pair, y-pair)
    __shared__ ulonglong2 tileB[KNN_TILE / 2];  // (z-pair, w-pair)

    const int tid  = threadIdx.x;
    const int w    = tid >> 5;
    const int lane = tid & 31;
    const int q    = blockIdx.x * KNN_WARPS + w;

    const float4 qp = g_pos4[q];
    const unsigned long long qx2 = pk2(qp.x, qp.x);
    const unsigned long long qy2 = pk2(qp.y, qp.y);
    const unsigned long long qz2 = pk2(qp.z, qp.z);
    const unsigned long long qw2 = pk2(qp.w, qp.w);
    const unsigned long long M2  = pk2(-2.0f, -2.0f);

    float bd = FINF;      // lane<16: l-th smallest distance
    int   bj = 0;
    float worst = FINF;   // current 16th smallest (warp-uniform)

    for (int t0 = 0; t0 < n; t0 += KNN_TILE) {
        for (int c = tid; c < KNN_TILE / 2; c += KNN_THREADS) {
            float4 p0 = g_pos4[t0 + 2 * c];
            float4 p1 = g_pos4[t0 + 2 * c + 1];
            tileA[c] = make_ulonglong2(pk2(p0.x, p1.x), pk2(p0.y, p1.y));
            tileB[c] = make_ulonglong2(pk2(p0.z, p1.z), pk2(p0.w, p1.w));
        }
        __syncthreads();

#pragma unroll 4
        for (int it = 0; it < KNN_TILE / 2; it += 32) {
            ulonglong2 A = tileA[it + lane];   // LDS.128
            ulonglong2 B = tileB[it + lane];   // LDS.128
            unsigned long long acc = mul2(qz2, B.x);
            acc = fma2(qy2, A.y, acc);
            acc = fma2(qx2, A.x, acc);
            unsigned long long dd = fma2(M2, acc, add2(qw2, B.y));
            float d0, d1;
            upk2(dd, d0, d1);

            unsigned m = __ballot_sync(FULLMASK, (d0 < worst) | (d1 < worst));
            while (m) {
                int src = __ffs(m) - 1;
                m &= m - 1;
                float e0 = __shfl_sync(FULLMASK, d0, src);
                float e1 = __shfl_sync(FULLMASK, d1, src);
                int j0 = t0 + 2 * (it + src);
                if (e0 < worst && j0 != q)
                    warp_insert(e0, j0, bd, bj, worst, lane);
                if (e1 < worst && j0 + 1 != q)
                    warp_insert(e1, j0 + 1, bd, bj, worst, lane);
            }
        }
        __syncthreads();
    }

    if (lane < KNN)
        g_knn[q * KNN + lane] = bj;
}

// ============================================================
// Kernel 2: B = x @ W1b ; C = x @ (W1a - W1b) + b1
// ============================================================
__global__ void feat_kernel(const float* __restrict__ x,
                            const float* __restrict__ W1,
                            const float* __restrict__ b1, int n) {
    int t = blockIdx.x * blockDim.x + threadIdx.x;
    int nn = t >> 6;
    int d  = t & 63;
    if (nn >= n) return;
    const float* xr = x + nn * CDIM;
    float a = 0.0f, b = 0.0f;
#pragma unroll 8
    for (int c = 0; c < CDIM; c++) {
        float xv = xr[c];                           // warp broadcast, L1-hot
        a = fmaf(xv, W1[c * CDIM + d], a);          // W1a
        b = fmaf(xv, W1[(CDIM + c) * CDIM + d], b); // W1b
    }
    g_B[t] = b;
    g_C[t] = a - b + b1[d];
}

// ============================================================
// Kernel 3: per-node: g[k] = relu(C_i + B_j) (one sync), then 16x64
// matvec via packed fma.rn.f32x2 + running max.
// g read as LDS.128 broadcast (2 packed pairs per load): LDS:FMA2 = 1:2.
// ============================================================
__global__ __launch_bounds__(64)
void edge_kernel(const float* __restrict__ W2,
                 const float* __restrict__ b2,
                 float* __restrict__ out, int n) {
    __shared__ __align__(16) float gs[KNN][CDIM];
    const int d = threadIdx.x;

    // pack W2 column d as 32 f32x2 pairs (W2[2e][d], W2[2e+1][d])
    unsigned long long w2p[CDIM / 2];
#pragma unroll
    for (int e2 = 0; e2 < CDIM / 2; e2++)
        w2p[e2] = pk2(W2[(2 * e2) * CDIM + d], W2[(2 * e2 + 1) * CDIM + d]);
    const float b2d = b2[d];

    const int n0 = blockIdx.x * NODES_PER_BLOCK;
    for (int i = 0; i < NODES_PER_BLOCK; i++) {
        const int nn = n0 + i;
        const float cv = g_C[nn * CDIM + d];

        int j[KNN];
#pragma unroll
        for (int k = 0; k < KNN; k++)
            j[k] = g_knn[nn * KNN + k];             // uniform, L1 broadcast
#pragma unroll
        for (int k = 0; k < KNN; k++)
            gs[k][d] = fmaxf(cv + g_B[j[k] * CDIM + d], 0.0f);
        __syncthreads();

        float m = -3.4e38f;
#pragma unroll
        for (int k = 0; k < KNN; k++) {
            const ulonglong2* gp = (const ulonglong2*)gs[k];
            unsigned long long acc0 = 0ULL, acc1 = 0ULL;
#pragma unroll
            for (int e4 = 0; e4 < CDIM / 4; e4++) {
                ulonglong2 gv = gp[e4];             // LDS.128 broadcast
                acc0 = fma2(gv.x, w2p[2 * e4 + 0], acc0);
                acc1 = fma2(gv.y, w2p[2 * e4 + 1], acc1);
            }
            float lo0, hi0, lo1, hi1;
            upk2(acc0, lo0, hi0);
            upk2(acc1, lo1, hi1);
            m = fmaxf(m, (lo0 + hi0) + (lo1 + hi1));
        }
        out[nn * CDIM + d] = m + b2d;
        __syncthreads();   // gs reused next node
    }
}

// ============================================================
extern "C" void kernel_launch(void* const* d_in, const int* in_sizes, int n_in,
                              void* d_out, int out_size) {
    const float* x   = (const float*)d_in[0];
    const float* pos = (const float*)d_in[1];
    const float* W1  = (const float*)d_in[2];
    const float* b1  = (const float*)d_in[3];
    const float* W2  = (const float*)d_in[4];
    const float* b2  = (const float*)d_in[5];
    float* out = (float*)d_out;

    int n = in_sizes[1] / 3;
    if (n > NMAX) n = NMAX;

    pack_pos_kernel<<<(n + 255) / 256, 256>>>(pos, n);
    knn_kernel<<<n / KNN_WARPS, KNN_THREADS>>>(n);
    feat_kernel<<<(n * CDIM + 255) / 256, 256>>>(x, W1, b1, n);
    edge_kernel<<<n / NODES_PER_BLOCK, CDIM>>>(W2, b2, out, n);
}